// round 14
// baseline (speedup 1.0000x reference)
#include <cuda_runtime.h>
#include <cuda_bf16.h>
#include <cstdint>

#define B_SZ   16
#define N_SEQ  2048
#define F_DIM  256
#define BNR    (B_SZ * N_SEQ)   // 32768 rows

// ---------------- device scratch (no runtime allocation allowed) ----------------
__device__ float g_v[(size_t)BNR * F_DIM];                 // V projection (fp32)
__device__ float g_s[(size_t)B_SZ * N_SEQ * N_SEQ];        // 268 MB scores (fp32)
__device__ __nv_bfloat16 g_rh[(size_t)BNR * F_DIM];        // relu(pos) hi/lo
__device__ __nv_bfloat16 g_rl[(size_t)BNR * F_DIM];
__device__ __nv_bfloat16 g_hh[(size_t)BNR * F_DIM];        // H hi/lo
__device__ __nv_bfloat16 g_hl[(size_t)BNR * F_DIM];
__device__ __nv_bfloat16 g_qh[(size_t)BNR * F_DIM];
__device__ __nv_bfloat16 g_ql[(size_t)BNR * F_DIM];
__device__ __nv_bfloat16 g_kh[(size_t)BNR * F_DIM];
__device__ __nv_bfloat16 g_kl[(size_t)BNR * F_DIM];
__device__ __nv_bfloat16 g_vth[(size_t)F_DIM * BNR];       // V^T hi  [F][BNR]
__device__ __nv_bfloat16 g_vtl[(size_t)F_DIM * BNR];       // V^T lo
__device__ __nv_bfloat16 g_ph[(size_t)B_SZ * N_SEQ * N_SEQ];
__device__ __nv_bfloat16 g_pl[(size_t)B_SZ * N_SEQ * N_SEQ];
// weight splits (each 256x256)
__device__ __nv_bfloat16 g_w2h[F_DIM * F_DIM], g_w2l[F_DIM * F_DIM];
__device__ __nv_bfloat16 g_wbh[F_DIM * F_DIM], g_wbl[F_DIM * F_DIM];  // Wk (used for q)
__device__ __nv_bfloat16 g_wch[F_DIM * F_DIM], g_wcl[F_DIM * F_DIM];  // Wq (used for k)
__device__ __nv_bfloat16 g_wdh[F_DIM * F_DIM], g_wdl[F_DIM * F_DIM];  // Wv

// ---------------- warp-MMA helpers (sm_75/80+ baseline; valid on compute_103) ----
__device__ __forceinline__ uint32_t smem_u32(const void* p) {
    uint32_t a;
    asm("{ .reg .u64 t; cvta.to.shared.u64 t, %1; cvt.u32.u64 %0, t; }" : "=r"(a) : "l"(p));
    return a;
}
__device__ __forceinline__ void cp16(uint32_t s, const void* g) {
    asm volatile("cp.async.cg.shared.global [%0], [%1], 16;" :: "r"(s), "l"(g) : "memory");
}
template<int N> __device__ __forceinline__ void cp_wait() {
    asm volatile("cp.async.wait_group %0;" :: "n"(N) : "memory");
}
__device__ __forceinline__ void cp_commit() {
    asm volatile("cp.async.commit_group;" ::: "memory");
}
__device__ __forceinline__ void ldsm4(uint32_t* r, uint32_t a) {
    asm volatile("ldmatrix.sync.aligned.m8n8.x4.shared.b16 {%0,%1,%2,%3}, [%4];"
        : "=r"(r[0]), "=r"(r[1]), "=r"(r[2]), "=r"(r[3]) : "r"(a));
}
__device__ __forceinline__ void mma16816(float* c, const uint32_t* a, const uint32_t* b) {
    asm volatile(
        "mma.sync.aligned.m16n8k16.row.col.f32.bf16.bf16.f32 "
        "{%0,%1,%2,%3}, {%4,%5,%6,%7}, {%8,%9}, {%0,%1,%2,%3};"
        : "+f"(c[0]), "+f"(c[1]), "+f"(c[2]), "+f"(c[3])
        : "r"(a[0]), "r"(a[1]), "r"(a[2]), "r"(a[3]), "r"(b[0]), "r"(b[1]));
}
__device__ __forceinline__ unsigned pk2(__nv_bfloat16 a, __nv_bfloat16 b) {
    __nv_bfloat162 t2; t2.x = a; t2.y = b;
    return *(unsigned*)&t2;
}
__device__ __forceinline__ void split1(float v, __nv_bfloat16& h, __nv_bfloat16& l) {
    h = __float2bfloat16(v);
    l = __float2bfloat16(v - __bfloat162float(h));
}

// ---------------- positional encoder: R = relu(p @ W1^T + b1) -> bf16 hi/lo ----------
__global__ void pos_split_kernel(const float* __restrict__ p, const float* __restrict__ W1,
                                 const float* __restrict__ b1,
                                 __nv_bfloat16* __restrict__ rh, __nv_bfloat16* __restrict__ rl) {
    const int gid = blockIdx.x * blockDim.x + threadIdx.x;   // BNR*64 threads
    const int i = gid >> 6;
    const int f0 = (gid & 63) * 4;
    const float p0 = __ldg(p + (size_t)i * 3 + 0);
    const float p1 = __ldg(p + (size_t)i * 3 + 1);
    const float p2 = __ldg(p + (size_t)i * 3 + 2);
    __nv_bfloat16 hv[4], lv[4];
#pragma unroll
    for (int j = 0; j < 4; j++) {
        const int f = f0 + j;
        float r = fmaf(p0, __ldg(W1 + f * 3 + 0),
                  fmaf(p1, __ldg(W1 + f * 3 + 1),
                  fmaf(p2, __ldg(W1 + f * 3 + 2), __ldg(b1 + f))));
        r = fmaxf(r, 0.0f);
        split1(r, hv[j], lv[j]);
    }
    const size_t o = (size_t)i * F_DIM + f0;
    *(uint2*)(rh + o) = *(uint2*)hv;
    *(uint2*)(rl + o) = *(uint2*)lv;
}

// ---------------- 4 weights fp32 -> bf16 hi/lo split, one launch ----------------
__global__ void split4_kernel(const float* __restrict__ s0, const float* __restrict__ s1,
                              const float* __restrict__ s2, const float* __restrict__ s3,
                              __nv_bfloat16* __restrict__ h0, __nv_bfloat16* __restrict__ l0,
                              __nv_bfloat16* __restrict__ h1, __nv_bfloat16* __restrict__ l1,
                              __nv_bfloat16* __restrict__ h2, __nv_bfloat16* __restrict__ l2,
                              __nv_bfloat16* __restrict__ h3, __nv_bfloat16* __restrict__ l3) {
    const float* s; __nv_bfloat16 *h, *l;
    switch (blockIdx.y) {
        case 0:  s = s0; h = h0; l = l0; break;
        case 1:  s = s1; h = h1; l = l1; break;
        case 2:  s = s2; h = h2; l = l2; break;
        default: s = s3; h = h3; l = l3; break;
    }
    size_t i = ((size_t)blockIdx.x * 256 + threadIdx.x) * 4;
    float4 v = *(const float4*)(s + i);
    float f[4] = {v.x, v.y, v.z, v.w};
    __nv_bfloat16 hv[4], lv[4];
#pragma unroll
    for (int j = 0; j < 4; j++) split1(f[j], hv[j], lv[j]);
    *(uint2*)(h + i) = *(uint2*)hv;
    *(uint2*)(l + i) = *(uint2*)lv;
}

// ---------------- V [BNR,F] fp32 -> V^T [F,BNR] bf16 hi/lo ----------------
__global__ void vt_kernel(const float* __restrict__ V,
                          __nv_bfloat16* __restrict__ th, __nv_bfloat16* __restrict__ tl) {
    __shared__ float t[32][33];
    const int m0 = blockIdx.y * 32, f0 = blockIdx.x * 32;
    const int tx = threadIdx.x, ty = threadIdx.y;   // 32 x 8
#pragma unroll
    for (int i = 0; i < 4; i++)
        t[ty + i * 8][tx] = V[(size_t)(m0 + ty + i * 8) * F_DIM + f0 + tx];
    __syncthreads();
#pragma unroll
    for (int i = 0; i < 4; i++) {
        float v = t[tx][ty + i * 8];
        __nv_bfloat16 h, l;
        split1(v, h, l);
        size_t o = (size_t)(f0 + ty + i * 8) * BNR + m0 + tx;
        th[o] = h; tl[o] = l;
    }
}

// ---------------- shared 3xBF16 mainloop config ----------------
// block tile 128x128, BK=32, 256 threads (8 warps, 4m x 2n), warp tile 32x64.
// smem row stride 80B: stride=20 words; r*20 mod 32 = {0,20,8,28,16,4,24,12},
// each ldmatrix row-fetch spans 4 consecutive banks -> the 8 rows of every 8x8
// matrix hit disjoint bank quads -> conflict-free LDSM. 2 buf x 4 arr x 128 x 80B
// = 80 KB -> 2 CTAs/SM.
#define MMA_RS     80                        // smem row stride bytes
#define MMA_ARR    (128 * MMA_RS)            // 10240
#define MMA_BUF    (4 * MMA_ARR)             // 40960
#define MMA_SMEM   (2 * MMA_BUF)             // 81920

// mainloop macro body (shared between mma3 / mma3p): accumulates into acc[2][8][4].
// Fragments via ldmatrix.x4: A = 4 ops/ks, B = 8 ops/ks (one x4 covers 2 n-groups:
// r0/r2 = b-frag of nt, r1/r3 = b-frag of nt+1).
#define MMA3_MAINLOOP(KTOT, LDA, LDB, ABASE, BBASE)                                   \
    const uint32_t sb = smem_u32(smem);                                               \
    const int lr = tid >> 1;                                                          \
    const int lc = (tid & 1) * 16;                                                    \
    auto load_buf = [&](int buf, int kc) {                                            \
        const size_t ga = (ABASE) + (size_t)lr * (LDA) + kc + lc;                     \
        const size_t gb = (BBASE) + (size_t)lr * (LDB) + kc + lc;                     \
        const uint32_t so = sb + buf * MMA_BUF + lr * MMA_RS + lc * 2;                \
        cp16(so,                   Ah + ga); cp16(so + 16,               Ah + ga + 8);\
        cp16(so + MMA_ARR,         Al + ga); cp16(so + MMA_ARR + 16,     Al + ga + 8);\
        cp16(so + 2 * MMA_ARR,     Bh + gb); cp16(so + 2 * MMA_ARR + 16, Bh + gb + 8);\
        cp16(so + 3 * MMA_ARR,     Bl + gb); cp16(so + 3 * MMA_ARR + 16, Bl + gb + 8);\
        cp_commit();                                                                  \
    };                                                                                \
    float acc[2][8][4];                                                               \
    _Pragma("unroll") for (int i = 0; i < 2; i++)                                     \
    _Pragma("unroll") for (int j = 0; j < 8; j++)                                     \
    _Pragma("unroll") for (int q = 0; q < 4; q++) acc[i][j][q] = 0.0f;                \
    const int lm = lane & 15;                                                         \
    const uint32_t lmo = (lane >> 4) * 16;                                            \
    const uint32_t aOff0 = (wy * 32 + lm) * MMA_RS + lmo;                             \
    const uint32_t bOff0 = 2 * MMA_ARR + (wx * 64 + lm) * MMA_RS + lmo;               \
    const int nCh = (KTOT) >> 5;                                                      \
    load_buf(0, 0);                                                                   \
    for (int c = 0; c < nCh; c++) {                                                   \
        if (c + 1 < nCh) { load_buf((c + 1) & 1, (c + 1) << 5); cp_wait<1>(); }       \
        else             { cp_wait<0>(); }                                            \
        __syncthreads();                                                              \
        const uint32_t s0 = sb + (c & 1) * MMA_BUF;                                   \
        _Pragma("unroll")                                                             \
        for (int ks = 0; ks < 2; ks++) {                                              \
            const uint32_t kadd = ks * 32;                                            \
            uint32_t ah[2][4], al2[2][4];                                             \
            ldsm4(ah[0],  s0 + aOff0 + kadd);                                         \
            ldsm4(ah[1],  s0 + aOff0 + 16 * MMA_RS + kadd);                           \
            ldsm4(al2[0], s0 + MMA_ARR + aOff0 + kadd);                               \
            ldsm4(al2[1], s0 + MMA_ARR + aOff0 + 16 * MMA_RS + kadd);                 \
            _Pragma("unroll")                                                         \
            for (int j = 0; j < 4; j++) {                                             \
                const uint32_t rb = s0 + bOff0 + j * (16 * MMA_RS) + kadd;            \
                uint32_t bh4[4], bl4[4];                                              \
                ldsm4(bh4, rb);                                                       \
                ldsm4(bl4, rb + MMA_ARR);                                             \
                uint32_t bA[2] = {bh4[0], bh4[2]}, bB[2] = {bh4[1], bh4[3]};          \
                uint32_t cA[2] = {bl4[0], bl4[2]}, cB[2] = {bl4[1], bl4[3]};          \
                mma16816(acc[0][2*j],   ah[0],  bA);                                  \
                mma16816(acc[1][2*j],   ah[1],  bA);                                  \
                mma16816(acc[0][2*j],   ah[0],  cA);                                  \
                mma16816(acc[1][2*j],   ah[1],  cA);                                  \
                mma16816(acc[0][2*j],   al2[0], bA);                                  \
                mma16816(acc[1][2*j],   al2[1], bA);                                  \
                mma16816(acc[0][2*j+1], ah[0],  bB);                                  \
                mma16816(acc[1][2*j+1], ah[1],  bB);                                  \
                mma16816(acc[0][2*j+1], ah[0],  cB);                                  \
                mma16816(acc[1][2*j+1], ah[1],  cB);                                  \
                mma16816(acc[0][2*j+1], al2[0], bB);                                  \
                mma16816(acc[1][2*j+1], al2[1], bB);                                  \
            }                                                                         \
        }                                                                             \
        __syncthreads();                                                              \
    }

// ---------------- attention 3xBF16 GEMM (fp32 out, alpha) ----------------
__global__ void __launch_bounds__(256, 2) mma3_kernel(
    const __nv_bfloat16* __restrict__ Ah, const __nv_bfloat16* __restrict__ Al,
    const __nv_bfloat16* __restrict__ Bh, const __nv_bfloat16* __restrict__ Bl,
    float* __restrict__ C, int K, int ldB, int ldC,
    size_t aBatch, size_t bBatch, size_t cBatch, float alpha)
{
    extern __shared__ __align__(16) char smem[];
    const int tid  = threadIdx.x;
    const int lane = tid & 31, wid = tid >> 5;
    const int wy = wid >> 1, wx = wid & 1;
    const int g = lane >> 2, t = lane & 3;

    const size_t aBase = (size_t)blockIdx.z * aBatch + (size_t)(blockIdx.y * 128) * K;
    const size_t bBase = (size_t)blockIdx.z * bBatch + (size_t)(blockIdx.x * 128) * ldB;
    float* Cb = C + (size_t)blockIdx.z * cBatch + (size_t)(blockIdx.y * 128) * ldC
                  + blockIdx.x * 128;

    MMA3_MAINLOOP(K, K, ldB, aBase, bBase)

#pragma unroll
    for (int mt = 0; mt < 2; mt++) {
        const int row = wy * 32 + mt * 16 + g;
#pragma unroll
        for (int nt = 0; nt < 8; nt++) {
            const int col = wx * 64 + nt * 8 + 2 * t;
            float2 v0 = make_float2(acc[mt][nt][0] * alpha, acc[mt][nt][1] * alpha);
            float2 v1 = make_float2(acc[mt][nt][2] * alpha, acc[mt][nt][3] * alpha);
            *(float2*)(Cb + (size_t)row * ldC + col)       = v0;
            *(float2*)(Cb + (size_t)(row + 8) * ldC + col) = v1;
        }
    }
}

// ---------------- projection 3xBF16 GEMM: K=256, N=256, bias, opt residual ------
// SPLIT_OUT: write bf16 hi/lo pair; else fp32. A [M,256] hi/lo, B = weight [256,256].
template<bool HAS_ADD, bool SPLIT_OUT>
__global__ void __launch_bounds__(256, 2) mma3p_kernel(
    const __nv_bfloat16* __restrict__ Ah, const __nv_bfloat16* __restrict__ Al,
    const __nv_bfloat16* __restrict__ Bh, const __nv_bfloat16* __restrict__ Bl,
    const float* __restrict__ bias, const float* __restrict__ X,
    float* __restrict__ Cf,
    __nv_bfloat16* __restrict__ Ch, __nv_bfloat16* __restrict__ Cl)
{
    extern __shared__ __align__(16) char smem[];
    const int tid  = threadIdx.x;
    const int lane = tid & 31, wid = tid >> 5;
    const int wy = wid >> 1, wx = wid & 1;
    const int g = lane >> 2, t = lane & 3;

    const int m0 = blockIdx.y * 128;
    const int n0 = blockIdx.x * 128;
    const size_t aBase = (size_t)m0 * F_DIM;
    const size_t bBase = (size_t)n0 * F_DIM;

    MMA3_MAINLOOP(F_DIM, F_DIM, F_DIM, aBase, bBase)

#pragma unroll
    for (int mt = 0; mt < 2; mt++) {
        const int r0 = m0 + wy * 32 + mt * 16 + g;
#pragma unroll
        for (int nt = 0; nt < 8; nt++) {
            const int gc = n0 + wx * 64 + nt * 8 + 2 * t;
            const float b0 = __ldg(bias + gc), b1 = __ldg(bias + gc + 1);
            float v00 = acc[mt][nt][0] + b0, v01 = acc[mt][nt][1] + b1;
            float v10 = acc[mt][nt][2] + b0, v11 = acc[mt][nt][3] + b1;
            if (HAS_ADD) {
                float2 x0 = *(const float2*)(X + (size_t)r0 * F_DIM + gc);
                float2 x1 = *(const float2*)(X + (size_t)(r0 + 8) * F_DIM + gc);
                v00 += x0.x; v01 += x0.y; v10 += x1.x; v11 += x1.y;
            }
            if (SPLIT_OUT) {
                __nv_bfloat16 h00, l00, h01, l01, h10, l10, h11, l11;
                split1(v00, h00, l00); split1(v01, h01, l01);
                split1(v10, h10, l10); split1(v11, h11, l11);
                *(unsigned*)(Ch + (size_t)r0 * F_DIM + gc)       = pk2(h00, h01);
                *(unsigned*)(Cl + (size_t)r0 * F_DIM + gc)       = pk2(l00, l01);
                *(unsigned*)(Ch + (size_t)(r0 + 8) * F_DIM + gc) = pk2(h10, h11);
                *(unsigned*)(Cl + (size_t)(r0 + 8) * F_DIM + gc) = pk2(l10, l11);
            } else {
                *(float2*)(Cf + (size_t)r0 * F_DIM + gc)       = make_float2(v00, v01);
                *(float2*)(Cf + (size_t)(r0 + 8) * F_DIM + gc) = make_float2(v10, v11);
            }
        }
    }
}

// ---------------- rowwise softmax + bf16 hi/lo split of P ----------------
__global__ void softmax_kernel(const float* __restrict__ S,
                               __nv_bfloat16* __restrict__ ph, __nv_bfloat16* __restrict__ pl) {
    __shared__ float red[8];
    const size_t row = blockIdx.x;
    const float4* r = (const float4*)(S + row * (size_t)N_SEQ);
    const int tid = threadIdx.x;        // 256 threads, 8 floats each
    float4 v0 = r[tid * 2], v1 = r[tid * 2 + 1];

    float m = fmaxf(fmaxf(fmaxf(v0.x, v0.y), fmaxf(v0.z, v0.w)),
                    fmaxf(fmaxf(v1.x, v1.y), fmaxf(v1.z, v1.w)));
#pragma unroll
    for (int o = 16; o; o >>= 1) m = fmaxf(m, __shfl_xor_sync(0xffffffffu, m, o));
    if ((tid & 31) == 0) red[tid >> 5] = m;
    __syncthreads();
    float mm = red[0];
#pragma unroll
    for (int i = 1; i < 8; i++) mm = fmaxf(mm, red[i]);
    __syncthreads();

    v0.x = __expf(v0.x - mm); v0.y = __expf(v0.y - mm);
    v0.z = __expf(v0.z - mm); v0.w = __expf(v0.w - mm);
    v1.x = __expf(v1.x - mm); v1.y = __expf(v1.y - mm);
    v1.z = __expf(v1.z - mm); v1.w = __expf(v1.w - mm);

    float s = ((v0.x + v0.y) + (v0.z + v0.w)) + ((v1.x + v1.y) + (v1.z + v1.w));
#pragma unroll
    for (int o = 16; o; o >>= 1) s += __shfl_xor_sync(0xffffffffu, s, o);
    if ((tid & 31) == 0) red[tid >> 5] = s;
    __syncthreads();
    float tot = ((red[0] + red[1]) + (red[2] + red[3])) +
                ((red[4] + red[5]) + (red[6] + red[7]));
    float inv = __frcp_rn(tot);

    float f[8] = {v0.x * inv, v0.y * inv, v0.z * inv, v0.w * inv,
                  v1.x * inv, v1.y * inv, v1.z * inv, v1.w * inv};
    __nv_bfloat16 h[8], l[8];
#pragma unroll
    for (int j = 0; j < 8; j++) split1(f[j], h[j], l[j]);
    const size_t base = row * (size_t)N_SEQ + tid * 8;
    uint4 H, L;
    H.x = pk2(h[0], h[1]); H.y = pk2(h[2], h[3]);
    H.z = pk2(h[4], h[5]); H.w = pk2(h[6], h[7]);
    L.x = pk2(l[0], l[1]); L.y = pk2(l[2], l[3]);
    L.z = pk2(l[4], l[5]); L.w = pk2(l[6], l[7]);
    *(uint4*)(ph + base) = H;
    *(uint4*)(pl + base) = L;
}

// ---------------- launch ----------------
extern "C" void kernel_launch(void* const* d_in, const int* in_sizes, int n_in,
                              void* d_out, int out_size) {
    const float* x  = (const float*)d_in[0];
    const float* p  = (const float*)d_in[1];
    const float* Wq = (const float*)d_in[2];
    const float* bq = (const float*)d_in[3];
    const float* Wk = (const float*)d_in[4];
    const float* bk = (const float*)d_in[5];
    const float* Wv = (const float*)d_in[6];
    const float* bv = (const float*)d_in[7];
    const float* W1 = (const float*)d_in[8];
    const float* b1 = (const float*)d_in[9];
    const float* W2 = (const float*)d_in[10];
    const float* b2 = (const float*)d_in[11];
    float* out = (float*)d_out;

    float *vbuf, *sbuf;
    __nv_bfloat16 *rh, *rl, *hh, *hl, *qh, *ql, *kh, *kl, *vth, *vtl, *ph, *pl;
    __nv_bfloat16 *w2h, *w2l, *wbh, *wbl, *wch, *wcl, *wdh, *wdl;
    cudaGetSymbolAddress((void**)&vbuf, g_v);
    cudaGetSymbolAddress((void**)&sbuf, g_s);
    cudaGetSymbolAddress((void**)&rh, g_rh);   cudaGetSymbolAddress((void**)&rl, g_rl);
    cudaGetSymbolAddress((void**)&hh, g_hh);   cudaGetSymbolAddress((void**)&hl, g_hl);
    cudaGetSymbolAddress((void**)&qh, g_qh);   cudaGetSymbolAddress((void**)&ql, g_ql);
    cudaGetSymbolAddress((void**)&kh, g_kh);   cudaGetSymbolAddress((void**)&kl, g_kl);
    cudaGetSymbolAddress((void**)&vth, g_vth); cudaGetSymbolAddress((void**)&vtl, g_vtl);
    cudaGetSymbolAddress((void**)&ph, g_ph);   cudaGetSymbolAddress((void**)&pl, g_pl);
    cudaGetSymbolAddress((void**)&w2h, g_w2h); cudaGetSymbolAddress((void**)&w2l, g_w2l);
    cudaGetSymbolAddress((void**)&wbh, g_wbh); cudaGetSymbolAddress((void**)&wbl, g_wbl);
    cudaGetSymbolAddress((void**)&wch, g_wch); cudaGetSymbolAddress((void**)&wcl, g_wcl);
    cudaGetSymbolAddress((void**)&wdh, g_wdh); cudaGetSymbolAddress((void**)&wdl, g_wdl);

    cudaFuncSetAttribute(mma3_kernel, cudaFuncAttributeMaxDynamicSharedMemorySize, MMA_SMEM);
    cudaFuncSetAttribute(mma3p_kernel<true, true>,
                         cudaFuncAttributeMaxDynamicSharedMemorySize, MMA_SMEM);
    cudaFuncSetAttribute(mma3p_kernel<false, true>,
                         cudaFuncAttributeMaxDynamicSharedMemorySize, MMA_SMEM);
    cudaFuncSetAttribute(mma3p_kernel<false, false>,
                         cudaFuncAttributeMaxDynamicSharedMemorySize, MMA_SMEM);

    // 1) R = relu(p @ W1^T + b1) -> bf16 hi/lo
    pos_split_kernel<<<(BNR * 64) / 256, 256>>>(p, W1, b1, rh, rl);

    // 1b) weight splits in one launch (reference swaps: q-proj uses Wk, k-proj uses Wq)
    split4_kernel<<<dim3((F_DIM * F_DIM) / 1024, 4), 256>>>(
        W2, Wk, Wq, Wv, w2h, w2l, wbh, wbl, wch, wcl, wdh, wdl);

    // 2) H = R @ W2^T + b2 + x  -> hi/lo
    mma3p_kernel<true, true><<<dim3(2, BNR / 128), 256, MMA_SMEM>>>(
        rh, rl, w2h, w2l, b2, x, nullptr, hh, hl);

    // 3) projections from H (all HMMA)
    mma3p_kernel<false, true><<<dim3(2, BNR / 128), 256, MMA_SMEM>>>(
        hh, hl, wbh, wbl, bk, nullptr, nullptr, qh, ql);        // q = H@Wk^T+bk
    mma3p_kernel<false, true><<<dim3(2, BNR / 128), 256, MMA_SMEM>>>(
        hh, hl, wch, wcl, bq, nullptr, nullptr, kh, kl);        // k = H@Wq^T+bq
    mma3p_kernel<false, false><<<dim3(2, BNR / 128), 256, MMA_SMEM>>>(
        hh, hl, wdh, wdl, bv, nullptr, vbuf, nullptr, nullptr); // v fp32

    // 4) V^T hi/lo
    vt_kernel<<<dim3(F_DIM / 32, BNR / 32), dim3(32, 8)>>>(vbuf, vth, vtl);

    // 5) S = QK^T / 16  (3xBF16 warp-MMA)
    mma3_kernel<<<dim3(16, 16, 16), 256, MMA_SMEM>>>(
        qh, ql, kh, kl, sbuf,
        F_DIM, F_DIM, N_SEQ,
        (size_t)N_SEQ * F_DIM, (size_t)N_SEQ * F_DIM, (size_t)N_SEQ * N_SEQ, 0.0625f);

    // 6) softmax + split P to bf16 hi/lo
    softmax_kernel<<<B_SZ * N_SEQ, 256>>>(sbuf, ph, pl);

    // 7) out = P @ V  (3xBF16 warp-MMA; B = V^T rows, ldB = BNR)
    mma3_kernel<<<dim3(F_DIM / 128, 16, 16), 256, MMA_SMEM>>>(
        ph, pl, vth, vtl, out,
        N_SEQ, BNR, F_DIM,
        (size_t)N_SEQ * N_SEQ, (size_t)N_SEQ, (size_t)N_SEQ * F_DIM, 1.0f);
}

// round 15
// speedup vs baseline: 1.2048x; 1.2048x over previous
#include <cuda_runtime.h>
#include <cuda_bf16.h>
#include <cuda_fp16.h>
#include <cstdint>

#define B_SZ   16
#define N_SEQ  2048
#define F_DIM  256
#define BNR    (B_SZ * N_SEQ)   // 32768 rows

// ---------------- device scratch (no runtime allocation allowed) ----------------
__device__ float g_v[(size_t)BNR * F_DIM];                 // V projection (fp32)
__device__ float g_s[(size_t)B_SZ * N_SEQ * N_SEQ];        // 268 MB scores (fp32)
__device__ __nv_bfloat16 g_rh[(size_t)BNR * F_DIM];        // relu(pos) hi/lo
__device__ __nv_bfloat16 g_rl[(size_t)BNR * F_DIM];
__device__ __nv_bfloat16 g_hh[(size_t)BNR * F_DIM];        // H hi/lo
__device__ __nv_bfloat16 g_hl[(size_t)BNR * F_DIM];
__device__ __nv_bfloat16 g_qh[(size_t)BNR * F_DIM];
__device__ __nv_bfloat16 g_ql[(size_t)BNR * F_DIM];
__device__ __nv_bfloat16 g_kh[(size_t)BNR * F_DIM];
__device__ __nv_bfloat16 g_kl[(size_t)BNR * F_DIM];
__device__ __half g_vth[(size_t)F_DIM * BNR];              // V^T hi (fp16)  [F][BNR]
__device__ __half g_vtl[(size_t)F_DIM * BNR];              // V^T lo (fp16)
__device__ __half g_p16[(size_t)B_SZ * N_SEQ * N_SEQ];     // P (fp16, single)
// weight splits (each 256x256)
__device__ __nv_bfloat16 g_w2h[F_DIM * F_DIM], g_w2l[F_DIM * F_DIM];
__device__ __nv_bfloat16 g_wbh[F_DIM * F_DIM], g_wbl[F_DIM * F_DIM];  // Wk (used for q)
__device__ __nv_bfloat16 g_wch[F_DIM * F_DIM], g_wcl[F_DIM * F_DIM];  // Wq (used for k)
__device__ __nv_bfloat16 g_wdh[F_DIM * F_DIM], g_wdl[F_DIM * F_DIM];  // Wv

// ---------------- warp-MMA helpers (sm_80+ baseline; valid on compute_103) ----
__device__ __forceinline__ uint32_t smem_u32(const void* p) {
    uint32_t a;
    asm("{ .reg .u64 t; cvta.to.shared.u64 t, %1; cvt.u32.u64 %0, t; }" : "=r"(a) : "l"(p));
    return a;
}
__device__ __forceinline__ void cp16(uint32_t s, const void* g) {
    asm volatile("cp.async.cg.shared.global [%0], [%1], 16;" :: "r"(s), "l"(g) : "memory");
}
template<int N> __device__ __forceinline__ void cp_wait() {
    asm volatile("cp.async.wait_group %0;" :: "n"(N) : "memory");
}
__device__ __forceinline__ void cp_commit() {
    asm volatile("cp.async.commit_group;" ::: "memory");
}
__device__ __forceinline__ uint32_t lds32(uint32_t a) {
    uint32_t v;
    asm volatile("ld.shared.b32 %0, [%1];" : "=r"(v) : "r"(a));
    return v;
}
__device__ __forceinline__ void mma16816(float* c, const uint32_t* a, const uint32_t* b) {
    asm volatile(
        "mma.sync.aligned.m16n8k16.row.col.f32.bf16.bf16.f32 "
        "{%0,%1,%2,%3}, {%4,%5,%6,%7}, {%8,%9}, {%0,%1,%2,%3};"
        : "+f"(c[0]), "+f"(c[1]), "+f"(c[2]), "+f"(c[3])
        : "r"(a[0]), "r"(a[1]), "r"(a[2]), "r"(a[3]), "r"(b[0]), "r"(b[1]));
}
__device__ __forceinline__ void mma16816h(float* c, const uint32_t* a, const uint32_t* b) {
    asm volatile(
        "mma.sync.aligned.m16n8k16.row.col.f32.f16.f16.f32 "
        "{%0,%1,%2,%3}, {%4,%5,%6,%7}, {%8,%9}, {%0,%1,%2,%3};"
        : "+f"(c[0]), "+f"(c[1]), "+f"(c[2]), "+f"(c[3])
        : "r"(a[0]), "r"(a[1]), "r"(a[2]), "r"(a[3]), "r"(b[0]), "r"(b[1]));
}
__device__ __forceinline__ unsigned pk2(__nv_bfloat16 a, __nv_bfloat16 b) {
    __nv_bfloat162 t2; t2.x = a; t2.y = b;
    return *(unsigned*)&t2;
}
__device__ __forceinline__ unsigned pk2h(__half a, __half b) {
    __half2 t2; t2.x = a; t2.y = b;
    return *(unsigned*)&t2;
}
__device__ __forceinline__ void split1(float v, __nv_bfloat16& h, __nv_bfloat16& l) {
    h = __float2bfloat16(v);
    l = __float2bfloat16(v - __bfloat162float(h));
}
__device__ __forceinline__ void split1h(float v, __half& h, __half& l) {
    h = __float2half_rn(v);
    l = __float2half_rn(v - __half2float(h));
}

// ---------------- positional encoder: R = relu(p @ W1^T + b1) -> bf16 hi/lo ----------
__global__ void pos_split_kernel(const float* __restrict__ p, const float* __restrict__ W1,
                                 const float* __restrict__ b1,
                                 __nv_bfloat16* __restrict__ rh, __nv_bfloat16* __restrict__ rl) {
    const int gid = blockIdx.x * blockDim.x + threadIdx.x;   // BNR*64 threads
    const int i = gid >> 6;
    const int f0 = (gid & 63) * 4;
    const float p0 = __ldg(p + (size_t)i * 3 + 0);
    const float p1 = __ldg(p + (size_t)i * 3 + 1);
    const float p2 = __ldg(p + (size_t)i * 3 + 2);
    __nv_bfloat16 hv[4], lv[4];
#pragma unroll
    for (int j = 0; j < 4; j++) {
        const int f = f0 + j;
        float r = fmaf(p0, __ldg(W1 + f * 3 + 0),
                  fmaf(p1, __ldg(W1 + f * 3 + 1),
                  fmaf(p2, __ldg(W1 + f * 3 + 2), __ldg(b1 + f))));
        r = fmaxf(r, 0.0f);
        split1(r, hv[j], lv[j]);
    }
    const size_t o = (size_t)i * F_DIM + f0;
    *(uint2*)(rh + o) = *(uint2*)hv;
    *(uint2*)(rl + o) = *(uint2*)lv;
}

// ---------------- 4 weights fp32 -> bf16 hi/lo split, one launch ----------------
__global__ void split4_kernel(const float* __restrict__ s0, const float* __restrict__ s1,
                              const float* __restrict__ s2, const float* __restrict__ s3,
                              __nv_bfloat16* __restrict__ h0, __nv_bfloat16* __restrict__ l0,
                              __nv_bfloat16* __restrict__ h1, __nv_bfloat16* __restrict__ l1,
                              __nv_bfloat16* __restrict__ h2, __nv_bfloat16* __restrict__ l2,
                              __nv_bfloat16* __restrict__ h3, __nv_bfloat16* __restrict__ l3) {
    const float* s; __nv_bfloat16 *h, *l;
    switch (blockIdx.y) {
        case 0:  s = s0; h = h0; l = l0; break;
        case 1:  s = s1; h = h1; l = l1; break;
        case 2:  s = s2; h = h2; l = l2; break;
        default: s = s3; h = h3; l = l3; break;
    }
    size_t i = ((size_t)blockIdx.x * 256 + threadIdx.x) * 4;
    float4 v = *(const float4*)(s + i);
    float f[4] = {v.x, v.y, v.z, v.w};
    __nv_bfloat16 hv[4], lv[4];
#pragma unroll
    for (int j = 0; j < 4; j++) split1(f[j], hv[j], lv[j]);
    *(uint2*)(h + i) = *(uint2*)hv;
    *(uint2*)(l + i) = *(uint2*)lv;
}

// ---------------- V [BNR,F] fp32 -> V^T [F,BNR] fp16 hi/lo ----------------
__global__ void vt_kernel(const float* __restrict__ V,
                          __half* __restrict__ th, __half* __restrict__ tl) {
    __shared__ float t[32][33];
    const int m0 = blockIdx.y * 32, f0 = blockIdx.x * 32;
    const int tx = threadIdx.x, ty = threadIdx.y;   // 32 x 8
#pragma unroll
    for (int i = 0; i < 4; i++)
        t[ty + i * 8][tx] = V[(size_t)(m0 + ty + i * 8) * F_DIM + f0 + tx];
    __syncthreads();
#pragma unroll
    for (int i = 0; i < 4; i++) {
        float v = t[tx][ty + i * 8];
        __half h, l;
        split1h(v, h, l);
        size_t o = (size_t)(f0 + ty + i * 8) * BNR + m0 + tx;
        th[o] = h; tl[o] = l;
    }
}

// ---------------- shared 3xBF16 mainloop config ----------------
// block tile 128x128, BK=32, 256 threads (8 warps, 4m x 2n), warp tile 32x64.
// smem row stride 80B: stride=20 words; r*20 mod 32 = {0,20,8,28,16,4,24,12} distinct,
// +t(0..3) covers all 32 banks -> conflict-free fragment loads. 2 buf x 4 arr x 128 x
// 80B = 80 KB -> 2 CTAs/SM.
#define MMA_RS     80                        // smem row stride bytes
#define MMA_ARR    (128 * MMA_RS)            // 10240
#define MMA_BUF    (4 * MMA_ARR)             // 40960
#define MMA_SMEM   (2 * MMA_BUF)             // 81920

// mainloop macro body (shared between mma3 / mma3p): accumulates into acc[2][8][4].
// B-fragments loaded per-nt to keep live registers ~100 (2 CTA/SM at 128-reg cap).
#define MMA3_MAINLOOP(KTOT, LDA, LDB, ABASE, BBASE)                                   \
    const uint32_t sb = smem_u32(smem);                                               \
    const int lr = tid >> 1;                                                          \
    const int lc = (tid & 1) * 16;                                                    \
    auto load_buf = [&](int buf, int kc) {                                            \
        const size_t ga = (ABASE) + (size_t)lr * (LDA) + kc + lc;                     \
        const size_t gb = (BBASE) + (size_t)lr * (LDB) + kc + lc;                     \
        const uint32_t so = sb + buf * MMA_BUF + lr * MMA_RS + lc * 2;                \
        cp16(so,                   Ah + ga); cp16(so + 16,               Ah + ga + 8);\
        cp16(so + MMA_ARR,         Al + ga); cp16(so + MMA_ARR + 16,     Al + ga + 8);\
        cp16(so + 2 * MMA_ARR,     Bh + gb); cp16(so + 2 * MMA_ARR + 16, Bh + gb + 8);\
        cp16(so + 3 * MMA_ARR,     Bl + gb); cp16(so + 3 * MMA_ARR + 16, Bl + gb + 8);\
        cp_commit();                                                                  \
    };                                                                                \
    float acc[2][8][4];                                                               \
    _Pragma("unroll") for (int i = 0; i < 2; i++)                                     \
    _Pragma("unroll") for (int j = 0; j < 8; j++)                                     \
    _Pragma("unroll") for (int q = 0; q < 4; q++) acc[i][j][q] = 0.0f;                \
    const int nCh = (KTOT) >> 5;                                                      \
    load_buf(0, 0);                                                                   \
    for (int c = 0; c < nCh; c++) {                                                   \
        if (c + 1 < nCh) { load_buf((c + 1) & 1, (c + 1) << 5); cp_wait<1>(); }       \
        else             { cp_wait<0>(); }                                            \
        __syncthreads();                                                              \
        const uint32_t s0 = sb + (c & 1) * MMA_BUF;                                   \
        _Pragma("unroll")                                                             \
        for (int ks = 0; ks < 2; ks++) {                                              \
            const uint32_t kb = ks * 32 + t * 4;                                      \
            uint32_t ah[2][4], al2[2][4];                                             \
            _Pragma("unroll")                                                         \
            for (int mt = 0; mt < 2; mt++) {                                          \
                const uint32_t ra = s0 + (wy * 32 + mt * 16 + g) * MMA_RS + kb;       \
                ah[mt][0]  = lds32(ra);                                               \
                ah[mt][1]  = lds32(ra + 8 * MMA_RS);                                  \
                ah[mt][2]  = lds32(ra + 16);                                          \
                ah[mt][3]  = lds32(ra + 8 * MMA_RS + 16);                             \
                al2[mt][0] = lds32(ra + MMA_ARR);                                     \
                al2[mt][1] = lds32(ra + MMA_ARR + 8 * MMA_RS);                        \
                al2[mt][2] = lds32(ra + MMA_ARR + 16);                                \
                al2[mt][3] = lds32(ra + MMA_ARR + 8 * MMA_RS + 16);                   \
            }                                                                         \
            _Pragma("unroll")                                                         \
            for (int nt = 0; nt < 8; nt++) {                                          \
                const uint32_t rb = s0 + 2 * MMA_ARR + (wx * 64 + nt * 8 + g) * MMA_RS + kb; \
                uint32_t bh[2], bl[2];                                                \
                bh[0] = lds32(rb);           bh[1] = lds32(rb + 16);                  \
                bl[0] = lds32(rb + MMA_ARR); bl[1] = lds32(rb + MMA_ARR + 16);        \
                mma16816(acc[0][nt], ah[0],  bh);                                     \
                mma16816(acc[1][nt], ah[1],  bh);                                     \
                mma16816(acc[0][nt], ah[0],  bl);                                     \
                mma16816(acc[1][nt], ah[1],  bl);                                     \
                mma16816(acc[0][nt], al2[0], bh);                                     \
                mma16816(acc[1][nt], al2[1], bh);                                     \
            }                                                                         \
        }                                                                             \
        __syncthreads();                                                              \
    }

// ---------------- attention 3xBF16 GEMM (fp32 out, alpha) — used for QK ----------
__global__ void __launch_bounds__(256, 2) mma3_kernel(
    const __nv_bfloat16* __restrict__ Ah, const __nv_bfloat16* __restrict__ Al,
    const __nv_bfloat16* __restrict__ Bh, const __nv_bfloat16* __restrict__ Bl,
    float* __restrict__ C, int K, int ldB, int ldC,
    size_t aBatch, size_t bBatch, size_t cBatch, float alpha)
{
    extern __shared__ __align__(16) char smem[];
    const int tid  = threadIdx.x;
    const int lane = tid & 31, wid = tid >> 5;
    const int wy = wid >> 1, wx = wid & 1;
    const int g = lane >> 2, t = lane & 3;

    const size_t aBase = (size_t)blockIdx.z * aBatch + (size_t)(blockIdx.y * 128) * K;
    const size_t bBase = (size_t)blockIdx.z * bBatch + (size_t)(blockIdx.x * 128) * ldB;
    float* Cb = C + (size_t)blockIdx.z * cBatch + (size_t)(blockIdx.y * 128) * ldC
                  + blockIdx.x * 128;

    MMA3_MAINLOOP(K, K, ldB, aBase, bBase)

#pragma unroll
    for (int mt = 0; mt < 2; mt++) {
        const int row = wy * 32 + mt * 16 + g;
#pragma unroll
        for (int nt = 0; nt < 8; nt++) {
            const int col = wx * 64 + nt * 8 + 2 * t;
            float2 v0 = make_float2(acc[mt][nt][0] * alpha, acc[mt][nt][1] * alpha);
            float2 v1 = make_float2(acc[mt][nt][2] * alpha, acc[mt][nt][3] * alpha);
            *(float2*)(Cb + (size_t)row * ldC + col)       = v0;
            *(float2*)(Cb + (size_t)(row + 8) * ldC + col) = v1;
        }
    }
}

// ---------------- projection 3xBF16 GEMM: K=256, N=256, bias, opt residual ------
// SPLIT_OUT: write bf16 hi/lo pair; else fp32. A [M,256] hi/lo, B = weight [256,256].
template<bool HAS_ADD, bool SPLIT_OUT>
__global__ void __launch_bounds__(256, 2) mma3p_kernel(
    const __nv_bfloat16* __restrict__ Ah, const __nv_bfloat16* __restrict__ Al,
    const __nv_bfloat16* __restrict__ Bh, const __nv_bfloat16* __restrict__ Bl,
    const float* __restrict__ bias, const float* __restrict__ X,
    float* __restrict__ Cf,
    __nv_bfloat16* __restrict__ Ch, __nv_bfloat16* __restrict__ Cl)
{
    extern __shared__ __align__(16) char smem[];
    const int tid  = threadIdx.x;
    const int lane = tid & 31, wid = tid >> 5;
    const int wy = wid >> 1, wx = wid & 1;
    const int g = lane >> 2, t = lane & 3;

    const int m0 = blockIdx.y * 128;
    const int n0 = blockIdx.x * 128;
    const size_t aBase = (size_t)m0 * F_DIM;
    const size_t bBase = (size_t)n0 * F_DIM;

    MMA3_MAINLOOP(F_DIM, F_DIM, F_DIM, aBase, bBase)

#pragma unroll
    for (int mt = 0; mt < 2; mt++) {
        const int r0 = m0 + wy * 32 + mt * 16 + g;
#pragma unroll
        for (int nt = 0; nt < 8; nt++) {
            const int gc = n0 + wx * 64 + nt * 8 + 2 * t;
            const float b0 = __ldg(bias + gc), b1 = __ldg(bias + gc + 1);
            float v00 = acc[mt][nt][0] + b0, v01 = acc[mt][nt][1] + b1;
            float v10 = acc[mt][nt][2] + b0, v11 = acc[mt][nt][3] + b1;
            if (HAS_ADD) {
                float2 x0 = *(const float2*)(X + (size_t)r0 * F_DIM + gc);
                float2 x1 = *(const float2*)(X + (size_t)(r0 + 8) * F_DIM + gc);
                v00 += x0.x; v01 += x0.y; v10 += x1.x; v11 += x1.y;
            }
            if (SPLIT_OUT) {
                __nv_bfloat16 h00, l00, h01, l01, h10, l10, h11, l11;
                split1(v00, h00, l00); split1(v01, h01, l01);
                split1(v10, h10, l10); split1(v11, h11, l11);
                *(unsigned*)(Ch + (size_t)r0 * F_DIM + gc)       = pk2(h00, h01);
                *(unsigned*)(Cl + (size_t)r0 * F_DIM + gc)       = pk2(l00, l01);
                *(unsigned*)(Ch + (size_t)(r0 + 8) * F_DIM + gc) = pk2(h10, h11);
                *(unsigned*)(Cl + (size_t)(r0 + 8) * F_DIM + gc) = pk2(l10, l11);
            } else {
                *(float2*)(Cf + (size_t)r0 * F_DIM + gc)       = make_float2(v00, v01);
                *(float2*)(Cf + (size_t)(r0 + 8) * F_DIM + gc) = make_float2(v10, v11);
            }
        }
    }
}

// ---------------- PV: 2-pass fp16 GEMM (P positive -> single-operand P is safe) -----
// out[128, 128-tile] = P[128, 2048] @ (Vh + Vl)[rows=f, cols=k]^T, 64 HMMA/warp/chunk.
// smem: 3 arrays (P, Vh, Vl) x 128 x 80B x 2 buf = 60 KB -> 2 CTAs/SM.
#define PV_ARR  MMA_ARR
#define PV_BUF  (3 * MMA_ARR)                // 30720
#define PV_SMEM (2 * PV_BUF)                 // 61440

__global__ void __launch_bounds__(256, 2) pv2_kernel(
    const __half* __restrict__ P, const __half* __restrict__ Vh,
    const __half* __restrict__ Vl, float* __restrict__ out)
{
    extern __shared__ __align__(16) char smem[];
    const int tid  = threadIdx.x;
    const int lane = tid & 31, wid = tid >> 5;
    const int wy = wid >> 1, wx = wid & 1;
    const int g = lane >> 2, t = lane & 3;
    const int bz = blockIdx.z;

    const size_t aBase = (size_t)bz * N_SEQ * N_SEQ + (size_t)(blockIdx.y * 128) * N_SEQ;
    const size_t bBase = (size_t)bz * N_SEQ + (size_t)(blockIdx.x * 128) * BNR;
    float* Cb = out + (size_t)bz * N_SEQ * F_DIM + (size_t)(blockIdx.y * 128) * F_DIM
                    + blockIdx.x * 128;

    const uint32_t sb = smem_u32(smem);
    const int lr = tid >> 1;
    const int lc = (tid & 1) * 16;
    auto load_buf = [&](int buf, int kc) {
        const size_t ga = aBase + (size_t)lr * N_SEQ + kc + lc;
        const size_t gb = bBase + (size_t)lr * BNR + kc + lc;
        const uint32_t so = sb + buf * PV_BUF + lr * MMA_RS + lc * 2;
        cp16(so,              P  + ga); cp16(so + 16,              P  + ga + 8);
        cp16(so + PV_ARR,     Vh + gb); cp16(so + PV_ARR + 16,     Vh + gb + 8);
        cp16(so + 2 * PV_ARR, Vl + gb); cp16(so + 2 * PV_ARR + 16, Vl + gb + 8);
        cp_commit();
    };

    float acc[2][8][4];
#pragma unroll
    for (int i = 0; i < 2; i++)
#pragma unroll
        for (int j = 0; j < 8; j++)
#pragma unroll
            for (int q = 0; q < 4; q++) acc[i][j][q] = 0.0f;

    const int nCh = N_SEQ >> 5;   // 64
    load_buf(0, 0);
    for (int c = 0; c < nCh; c++) {
        if (c + 1 < nCh) { load_buf((c + 1) & 1, (c + 1) << 5); cp_wait<1>(); }
        else             { cp_wait<0>(); }
        __syncthreads();
        const uint32_t s0 = sb + (c & 1) * PV_BUF;
#pragma unroll
        for (int ks = 0; ks < 2; ks++) {
            const uint32_t kb = ks * 32 + t * 4;
            uint32_t ap[2][4];
#pragma unroll
            for (int mt = 0; mt < 2; mt++) {
                const uint32_t ra = s0 + (wy * 32 + mt * 16 + g) * MMA_RS + kb;
                ap[mt][0] = lds32(ra);
                ap[mt][1] = lds32(ra + 8 * MMA_RS);
                ap[mt][2] = lds32(ra + 16);
                ap[mt][3] = lds32(ra + 8 * MMA_RS + 16);
            }
#pragma unroll
            for (int nt = 0; nt < 8; nt++) {
                const uint32_t rb = s0 + PV_ARR + (wx * 64 + nt * 8 + g) * MMA_RS + kb;
                uint32_t bh[2], bl[2];
                bh[0] = lds32(rb);          bh[1] = lds32(rb + 16);
                bl[0] = lds32(rb + PV_ARR); bl[1] = lds32(rb + PV_ARR + 16);
                mma16816h(acc[0][nt], ap[0], bh);
                mma16816h(acc[1][nt], ap[1], bh);
                mma16816h(acc[0][nt], ap[0], bl);
                mma16816h(acc[1][nt], ap[1], bl);
            }
        }
        __syncthreads();
    }

#pragma unroll
    for (int mt = 0; mt < 2; mt++) {
        const int row = wy * 32 + mt * 16 + g;
#pragma unroll
        for (int nt = 0; nt < 8; nt++) {
            const int col = wx * 64 + nt * 8 + 2 * t;
            *(float2*)(Cb + (size_t)row * F_DIM + col) =
                make_float2(acc[mt][nt][0], acc[mt][nt][1]);
            *(float2*)(Cb + (size_t)(row + 8) * F_DIM + col) =
                make_float2(acc[mt][nt][2], acc[mt][nt][3]);
        }
    }
}

// ---------------- rowwise softmax -> P fp16 (single) ----------------
__global__ void softmax_kernel(const float* __restrict__ S, __half* __restrict__ ph) {
    __shared__ float red[8];
    const size_t row = blockIdx.x;
    const float4* r = (const float4*)(S + row * (size_t)N_SEQ);
    const int tid = threadIdx.x;        // 256 threads, 8 floats each
    float4 v0 = r[tid * 2], v1 = r[tid * 2 + 1];

    float m = fmaxf(fmaxf(fmaxf(v0.x, v0.y), fmaxf(v0.z, v0.w)),
                    fmaxf(fmaxf(v1.x, v1.y), fmaxf(v1.z, v1.w)));
#pragma unroll
    for (int o = 16; o; o >>= 1) m = fmaxf(m, __shfl_xor_sync(0xffffffffu, m, o));
    if ((tid & 31) == 0) red[tid >> 5] = m;
    __syncthreads();
    float mm = red[0];
#pragma unroll
    for (int i = 1; i < 8; i++) mm = fmaxf(mm, red[i]);
    __syncthreads();

    v0.x = __expf(v0.x - mm); v0.y = __expf(v0.y - mm);
    v0.z = __expf(v0.z - mm); v0.w = __expf(v0.w - mm);
    v1.x = __expf(v1.x - mm); v1.y = __expf(v1.y - mm);
    v1.z = __expf(v1.z - mm); v1.w = __expf(v1.w - mm);

    float s = ((v0.x + v0.y) + (v0.z + v0.w)) + ((v1.x + v1.y) + (v1.z + v1.w));
#pragma unroll
    for (int o = 16; o; o >>= 1) s += __shfl_xor_sync(0xffffffffu, s, o);
    if ((tid & 31) == 0) red[tid >> 5] = s;
    __syncthreads();
    float tot = ((red[0] + red[1]) + (red[2] + red[3])) +
                ((red[4] + red[5]) + (red[6] + red[7]));
    float inv = __frcp_rn(tot);

    float f[8] = {v0.x * inv, v0.y * inv, v0.z * inv, v0.w * inv,
                  v1.x * inv, v1.y * inv, v1.z * inv, v1.w * inv};
    __half h[8];
#pragma unroll
    for (int j = 0; j < 8; j++) h[j] = __float2half_rn(f[j]);
    const size_t base = row * (size_t)N_SEQ + tid * 8;
    uint4 H;
    H.x = pk2h(h[0], h[1]); H.y = pk2h(h[2], h[3]);
    H.z = pk2h(h[4], h[5]); H.w = pk2h(h[6], h[7]);
    *(uint4*)(ph + base) = H;
}

// ---------------- launch ----------------
extern "C" void kernel_launch(void* const* d_in, const int* in_sizes, int n_in,
                              void* d_out, int out_size) {
    const float* x  = (const float*)d_in[0];
    const float* p  = (const float*)d_in[1];
    const float* Wq = (const float*)d_in[2];
    const float* bq = (const float*)d_in[3];
    const float* Wk = (const float*)d_in[4];
    const float* bk = (const float*)d_in[5];
    const float* Wv = (const float*)d_in[6];
    const float* bv = (const float*)d_in[7];
    const float* W1 = (const float*)d_in[8];
    const float* b1 = (const float*)d_in[9];
    const float* W2 = (const float*)d_in[10];
    const float* b2 = (const float*)d_in[11];
    float* out = (float*)d_out;

    float *vbuf, *sbuf;
    __nv_bfloat16 *rh, *rl, *hh, *hl, *qh, *ql, *kh, *kl;
    __half *vth, *vtl, *p16;
    __nv_bfloat16 *w2h, *w2l, *wbh, *wbl, *wch, *wcl, *wdh, *wdl;
    cudaGetSymbolAddress((void**)&vbuf, g_v);
    cudaGetSymbolAddress((void**)&sbuf, g_s);
    cudaGetSymbolAddress((void**)&rh, g_rh);   cudaGetSymbolAddress((void**)&rl, g_rl);
    cudaGetSymbolAddress((void**)&hh, g_hh);   cudaGetSymbolAddress((void**)&hl, g_hl);
    cudaGetSymbolAddress((void**)&qh, g_qh);   cudaGetSymbolAddress((void**)&ql, g_ql);
    cudaGetSymbolAddress((void**)&kh, g_kh);   cudaGetSymbolAddress((void**)&kl, g_kl);
    cudaGetSymbolAddress((void**)&vth, g_vth); cudaGetSymbolAddress((void**)&vtl, g_vtl);
    cudaGetSymbolAddress((void**)&p16, g_p16);
    cudaGetSymbolAddress((void**)&w2h, g_w2h); cudaGetSymbolAddress((void**)&w2l, g_w2l);
    cudaGetSymbolAddress((void**)&wbh, g_wbh); cudaGetSymbolAddress((void**)&wbl, g_wbl);
    cudaGetSymbolAddress((void**)&wch, g_wch); cudaGetSymbolAddress((void**)&wcl, g_wcl);
    cudaGetSymbolAddress((void**)&wdh, g_wdh); cudaGetSymbolAddress((void**)&wdl, g_wdl);

    cudaFuncSetAttribute(mma3_kernel, cudaFuncAttributeMaxDynamicSharedMemorySize, MMA_SMEM);
    cudaFuncSetAttribute(mma3p_kernel<true, true>,
                         cudaFuncAttributeMaxDynamicSharedMemorySize, MMA_SMEM);
    cudaFuncSetAttribute(mma3p_kernel<false, true>,
                         cudaFuncAttributeMaxDynamicSharedMemorySize, MMA_SMEM);
    cudaFuncSetAttribute(mma3p_kernel<false, false>,
                         cudaFuncAttributeMaxDynamicSharedMemorySize, MMA_SMEM);
    cudaFuncSetAttribute(pv2_kernel, cudaFuncAttributeMaxDynamicSharedMemorySize, PV_SMEM);

    // 1) R = relu(p @ W1^T + b1) -> bf16 hi/lo
    pos_split_kernel<<<(BNR * 64) / 256, 256>>>(p, W1, b1, rh, rl);

    // 1b) weight splits in one launch (reference swaps: q-proj uses Wk, k-proj uses Wq)
    split4_kernel<<<dim3((F_DIM * F_DIM) / 1024, 4), 256>>>(
        W2, Wk, Wq, Wv, w2h, w2l, wbh, wbl, wch, wcl, wdh, wdl);

    // 2) H = R @ W2^T + b2 + x  -> hi/lo
    mma3p_kernel<true, true><<<dim3(2, BNR / 128), 256, MMA_SMEM>>>(
        rh, rl, w2h, w2l, b2, x, nullptr, hh, hl);

    // 3) projections from H (all HMMA)
    mma3p_kernel<false, true><<<dim3(2, BNR / 128), 256, MMA_SMEM>>>(
        hh, hl, wbh, wbl, bk, nullptr, nullptr, qh, ql);        // q = H@Wk^T+bk
    mma3p_kernel<false, true><<<dim3(2, BNR / 128), 256, MMA_SMEM>>>(
        hh, hl, wch, wcl, bq, nullptr, nullptr, kh, kl);        // k = H@Wq^T+bq
    mma3p_kernel<false, false><<<dim3(2, BNR / 128), 256, MMA_SMEM>>>(
        hh, hl, wdh, wdl, bv, nullptr, vbuf, nullptr, nullptr); // v fp32

    // 4) V^T fp16 hi/lo
    vt_kernel<<<dim3(F_DIM / 32, BNR / 32), dim3(32, 8)>>>(vbuf, vth, vtl);

    // 5) S = QK^T / 16  (3xBF16 warp-MMA)
    mma3_kernel<<<dim3(16, 16, 16), 256, MMA_SMEM>>>(
        qh, ql, kh, kl, sbuf,
        F_DIM, F_DIM, N_SEQ,
        (size_t)N_SEQ * F_DIM, (size_t)N_SEQ * F_DIM, (size_t)N_SEQ * N_SEQ, 0.0625f);

    // 6) softmax -> P fp16 (single operand; positivity bounds the rounding error)
    softmax_kernel<<<B_SZ * N_SEQ, 256>>>(sbuf, p16);

    // 7) out = P @ V  (2-pass fp16 warp-MMA)
    pv2_kernel<<<dim3(F_DIM / 128, 16, 16), 256, PV_SMEM>>>(p16, vth, vtl, out);
}

// round 16
// speedup vs baseline: 1.7563x; 1.4577x over previous
#include <cuda_runtime.h>
#include <cuda_bf16.h>
#include <cuda_fp16.h>
#include <cstdint>

#define B_SZ   16
#define N_SEQ  2048
#define F_DIM  256
#define BNR    (B_SZ * N_SEQ)   // 32768 rows

// ---------------- device scratch (no runtime allocation allowed) ----------------
__device__ float g_v[(size_t)BNR * F_DIM];                 // V projection (fp32)
__device__ float g_s[(size_t)B_SZ * N_SEQ * N_SEQ];        // 268 MB scores (fp32)
__device__ __nv_bfloat16 g_rh[(size_t)BNR * F_DIM];        // relu(pos) hi/lo
__device__ __nv_bfloat16 g_rl[(size_t)BNR * F_DIM];
__device__ __nv_bfloat16 g_hh[(size_t)BNR * F_DIM];        // H hi/lo
__device__ __nv_bfloat16 g_hl[(size_t)BNR * F_DIM];
__device__ __half g_q16[(size_t)BNR * F_DIM];              // q (fp16 single)
__device__ __half g_k16[(size_t)BNR * F_DIM];              // k (fp16 single)
__device__ __half g_vt16[(size_t)F_DIM * BNR];             // V^T (fp16 single) [F][BNR]
__device__ __half g_p16[(size_t)B_SZ * N_SEQ * N_SEQ];     // P (fp16 single)
// weight splits (each 256x256)
__device__ __nv_bfloat16 g_w2h[F_DIM * F_DIM], g_w2l[F_DIM * F_DIM];
__device__ __nv_bfloat16 g_wbh[F_DIM * F_DIM], g_wbl[F_DIM * F_DIM];  // Wk (used for q)
__device__ __nv_bfloat16 g_wch[F_DIM * F_DIM], g_wcl[F_DIM * F_DIM];  // Wq (used for k)
__device__ __nv_bfloat16 g_wdh[F_DIM * F_DIM], g_wdl[F_DIM * F_DIM];  // Wv

// ---------------- warp-MMA helpers (sm_80+ baseline; valid on compute_103) ----
__device__ __forceinline__ uint32_t smem_u32(const void* p) {
    uint32_t a;
    asm("{ .reg .u64 t; cvta.to.shared.u64 t, %1; cvt.u32.u64 %0, t; }" : "=r"(a) : "l"(p));
    return a;
}
__device__ __forceinline__ void cp16(uint32_t s, const void* g) {
    asm volatile("cp.async.cg.shared.global [%0], [%1], 16;" :: "r"(s), "l"(g) : "memory");
}
template<int N> __device__ __forceinline__ void cp_wait() {
    asm volatile("cp.async.wait_group %0;" :: "n"(N) : "memory");
}
__device__ __forceinline__ void cp_commit() {
    asm volatile("cp.async.commit_group;" ::: "memory");
}
__device__ __forceinline__ uint32_t lds32(uint32_t a) {
    uint32_t v;
    asm volatile("ld.shared.b32 %0, [%1];" : "=r"(v) : "r"(a));
    return v;
}
__device__ __forceinline__ void mma16816(float* c, const uint32_t* a, const uint32_t* b) {
    asm volatile(
        "mma.sync.aligned.m16n8k16.row.col.f32.bf16.bf16.f32 "
        "{%0,%1,%2,%3}, {%4,%5,%6,%7}, {%8,%9}, {%0,%1,%2,%3};"
        : "+f"(c[0]), "+f"(c[1]), "+f"(c[2]), "+f"(c[3])
        : "r"(a[0]), "r"(a[1]), "r"(a[2]), "r"(a[3]), "r"(b[0]), "r"(b[1]));
}
__device__ __forceinline__ void mma16816h(float* c, const uint32_t* a, const uint32_t* b) {
    asm volatile(
        "mma.sync.aligned.m16n8k16.row.col.f32.f16.f16.f32 "
        "{%0,%1,%2,%3}, {%4,%5,%6,%7}, {%8,%9}, {%0,%1,%2,%3};"
        : "+f"(c[0]), "+f"(c[1]), "+f"(c[2]), "+f"(c[3])
        : "r"(a[0]), "r"(a[1]), "r"(a[2]), "r"(a[3]), "r"(b[0]), "r"(b[1]));
}
__device__ __forceinline__ unsigned pk2(__nv_bfloat16 a, __nv_bfloat16 b) {
    __nv_bfloat162 t2; t2.x = a; t2.y = b;
    return *(unsigned*)&t2;
}
__device__ __forceinline__ unsigned pk2h(__half a, __half b) {
    __half2 t2; t2.x = a; t2.y = b;
    return *(unsigned*)&t2;
}
__device__ __forceinline__ void split1(float v, __nv_bfloat16& h, __nv_bfloat16& l) {
    h = __float2bfloat16(v);
    l = __float2bfloat16(v - __bfloat162float(h));
}

// ---------------- positional encoder: R = relu(p @ W1^T + b1) -> bf16 hi/lo ----------
__global__ void pos_split_kernel(const float* __restrict__ p, const float* __restrict__ W1,
                                 const float* __restrict__ b1,
                                 __nv_bfloat16* __restrict__ rh, __nv_bfloat16* __restrict__ rl) {
    const int gid = blockIdx.x * blockDim.x + threadIdx.x;   // BNR*64 threads
    const int i = gid >> 6;
    const int f0 = (gid & 63) * 4;
    const float p0 = __ldg(p + (size_t)i * 3 + 0);
    const float p1 = __ldg(p + (size_t)i * 3 + 1);
    const float p2 = __ldg(p + (size_t)i * 3 + 2);
    __nv_bfloat16 hv[4], lv[4];
#pragma unroll
    for (int j = 0; j < 4; j++) {
        const int f = f0 + j;
        float r = fmaf(p0, __ldg(W1 + f * 3 + 0),
                  fmaf(p1, __ldg(W1 + f * 3 + 1),
                  fmaf(p2, __ldg(W1 + f * 3 + 2), __ldg(b1 + f))));
        r = fmaxf(r, 0.0f);
        split1(r, hv[j], lv[j]);
    }
    const size_t o = (size_t)i * F_DIM + f0;
    *(uint2*)(rh + o) = *(uint2*)hv;
    *(uint2*)(rl + o) = *(uint2*)lv;
}

// ---------------- 4 weights fp32 -> bf16 hi/lo split, one launch ----------------
__global__ void split4_kernel(const float* __restrict__ s0, const float* __restrict__ s1,
                              const float* __restrict__ s2, const float* __restrict__ s3,
                              __nv_bfloat16* __restrict__ h0, __nv_bfloat16* __restrict__ l0,
                              __nv_bfloat16* __restrict__ h1, __nv_bfloat16* __restrict__ l1,
                              __nv_bfloat16* __restrict__ h2, __nv_bfloat16* __restrict__ l2,
                              __nv_bfloat16* __restrict__ h3, __nv_bfloat16* __restrict__ l3) {
    const float* s; __nv_bfloat16 *h, *l;
    switch (blockIdx.y) {
        case 0:  s = s0; h = h0; l = l0; break;
        case 1:  s = s1; h = h1; l = l1; break;
        case 2:  s = s2; h = h2; l = l2; break;
        default: s = s3; h = h3; l = l3; break;
    }
    size_t i = ((size_t)blockIdx.x * 256 + threadIdx.x) * 4;
    float4 v = *(const float4*)(s + i);
    float f[4] = {v.x, v.y, v.z, v.w};
    __nv_bfloat16 hv[4], lv[4];
#pragma unroll
    for (int j = 0; j < 4; j++) split1(f[j], hv[j], lv[j]);
    *(uint2*)(h + i) = *(uint2*)hv;
    *(uint2*)(l + i) = *(uint2*)lv;
}

// ---------------- V [BNR,F] fp32 -> V^T [F,BNR] fp16 single ----------------
__global__ void vt_kernel(const float* __restrict__ V, __half* __restrict__ t16) {
    __shared__ float t[32][33];
    const int m0 = blockIdx.y * 32, f0 = blockIdx.x * 32;
    const int tx = threadIdx.x, ty = threadIdx.y;   // 32 x 8
#pragma unroll
    for (int i = 0; i < 4; i++)
        t[ty + i * 8][tx] = V[(size_t)(m0 + ty + i * 8) * F_DIM + f0 + tx];
    __syncthreads();
#pragma unroll
    for (int i = 0; i < 4; i++) {
        float v = t[tx][ty + i * 8];
        size_t o = (size_t)(f0 + ty + i * 8) * BNR + m0 + tx;
        t16[o] = __float2half_rn(v);
    }
}

// ---------------- shared mainloop config ----------------
// block tile 128x128, BK=32, 256 threads (8 warps, 4m x 2n), warp tile 32x64.
// smem row stride 80B: stride=20 words; r*20 mod 32 = {0,20,8,28,16,4,24,12} distinct,
// +t(0..3) covers all 32 banks -> conflict-free fragment loads.
#define MMA_RS     80                        // smem row stride bytes
#define MMA_ARR    (128 * MMA_RS)            // 10240
#define MMA_BUF    (4 * MMA_ARR)             // 40960 (3-pass: 4 arrays)
#define MMA_SMEM   (2 * MMA_BUF)             // 81920
#define M1_BUF     (2 * MMA_ARR)             // 20480 (1-pass: 2 arrays)
#define M1_SMEM    (2 * M1_BUF)              // 40960

// 3xBF16 mainloop (projections): accumulates into acc[2][8][4].
#define MMA3_MAINLOOP(KTOT, LDA, LDB, ABASE, BBASE)                                   \
    const uint32_t sb = smem_u32(smem);                                               \
    const int lr = tid >> 1;                                                          \
    const int lc = (tid & 1) * 16;                                                    \
    auto load_buf = [&](int buf, int kc) {                                            \
        const size_t ga = (ABASE) + (size_t)lr * (LDA) + kc + lc;                     \
        const size_t gb = (BBASE) + (size_t)lr * (LDB) + kc + lc;                     \
        const uint32_t so = sb + buf * MMA_BUF + lr * MMA_RS + lc * 2;                \
        cp16(so,                   Ah + ga); cp16(so + 16,               Ah + ga + 8);\
        cp16(so + MMA_ARR,         Al + ga); cp16(so + MMA_ARR + 16,     Al + ga + 8);\
        cp16(so + 2 * MMA_ARR,     Bh + gb); cp16(so + 2 * MMA_ARR + 16, Bh + gb + 8);\
        cp16(so + 3 * MMA_ARR,     Bl + gb); cp16(so + 3 * MMA_ARR + 16, Bl + gb + 8);\
        cp_commit();                                                                  \
    };                                                                                \
    float acc[2][8][4];                                                               \
    _Pragma("unroll") for (int i = 0; i < 2; i++)                                     \
    _Pragma("unroll") for (int j = 0; j < 8; j++)                                     \
    _Pragma("unroll") for (int q = 0; q < 4; q++) acc[i][j][q] = 0.0f;                \
    const int nCh = (KTOT) >> 5;                                                      \
    load_buf(0, 0);                                                                   \
    for (int c = 0; c < nCh; c++) {                                                   \
        if (c + 1 < nCh) { load_buf((c + 1) & 1, (c + 1) << 5); cp_wait<1>(); }       \
        else             { cp_wait<0>(); }                                            \
        __syncthreads();                                                              \
        const uint32_t s0 = sb + (c & 1) * MMA_BUF;                                   \
        _Pragma("unroll")                                                             \
        for (int ks = 0; ks < 2; ks++) {                                              \
            const uint32_t kb = ks * 32 + t * 4;                                      \
            uint32_t ah[2][4], al2[2][4];                                             \
            _Pragma("unroll")                                                         \
            for (int mt = 0; mt < 2; mt++) {                                          \
                const uint32_t ra = s0 + (wy * 32 + mt * 16 + g) * MMA_RS + kb;       \
                ah[mt][0]  = lds32(ra);                                               \
                ah[mt][1]  = lds32(ra + 8 * MMA_RS);                                  \
                ah[mt][2]  = lds32(ra + 16);                                          \
                ah[mt][3]  = lds32(ra + 8 * MMA_RS + 16);                             \
                al2[mt][0] = lds32(ra + MMA_ARR);                                     \
                al2[mt][1] = lds32(ra + MMA_ARR + 8 * MMA_RS);                        \
                al2[mt][2] = lds32(ra + MMA_ARR + 16);                                \
                al2[mt][3] = lds32(ra + MMA_ARR + 8 * MMA_RS + 16);                   \
            }                                                                         \
            _Pragma("unroll")                                                         \
            for (int nt = 0; nt < 8; nt++) {                                          \
                const uint32_t rb = s0 + 2 * MMA_ARR + (wx * 64 + nt * 8 + g) * MMA_RS + kb; \
                uint32_t bh[2], bl[2];                                                \
                bh[0] = lds32(rb);           bh[1] = lds32(rb + 16);                  \
                bl[0] = lds32(rb + MMA_ARR); bl[1] = lds32(rb + MMA_ARR + 16);        \
                mma16816(acc[0][nt], ah[0],  bh);                                     \
                mma16816(acc[1][nt], ah[1],  bh);                                     \
                mma16816(acc[0][nt], ah[0],  bl);                                     \
                mma16816(acc[1][nt], ah[1],  bl);                                     \
                mma16816(acc[0][nt], al2[0], bh);                                     \
                mma16816(acc[1][nt], al2[1], bh);                                     \
            }                                                                         \
        }                                                                             \
        __syncthreads();                                                              \
    }

// ---------------- 1-pass fp16 GEMM (QK and PV): C = alpha * A @ B^T ----------------
__global__ void __launch_bounds__(256, 2) mma1_kernel(
    const __half* __restrict__ A, const __half* __restrict__ B,
    float* __restrict__ C, int K, int ldB, int ldC,
    size_t aBatch, size_t bBatch, size_t cBatch, float alpha)
{
    extern __shared__ __align__(16) char smem[];
    const int tid  = threadIdx.x;
    const int lane = tid & 31, wid = tid >> 5;
    const int wy = wid >> 1, wx = wid & 1;
    const int g = lane >> 2, t = lane & 3;

    const size_t aBase = (size_t)blockIdx.z * aBatch + (size_t)(blockIdx.y * 128) * K;
    const size_t bBase = (size_t)blockIdx.z * bBatch + (size_t)(blockIdx.x * 128) * ldB;
    float* Cb = C + (size_t)blockIdx.z * cBatch + (size_t)(blockIdx.y * 128) * ldC
                  + blockIdx.x * 128;

    const uint32_t sb = smem_u32(smem);
    const int lr = tid >> 1;
    const int lc = (tid & 1) * 16;
    auto load_buf = [&](int buf, int kc) {
        const size_t ga = aBase + (size_t)lr * K   + kc + lc;
        const size_t gb = bBase + (size_t)lr * ldB + kc + lc;
        const uint32_t so = sb + buf * M1_BUF + lr * MMA_RS + lc * 2;
        cp16(so,           A + ga); cp16(so + 16,           A + ga + 8);
        cp16(so + MMA_ARR, B + gb); cp16(so + MMA_ARR + 16, B + gb + 8);
        cp_commit();
    };

    float acc[2][8][4];
#pragma unroll
    for (int i = 0; i < 2; i++)
#pragma unroll
        for (int j = 0; j < 8; j++)
#pragma unroll
            for (int q = 0; q < 4; q++) acc[i][j][q] = 0.0f;

    const int nCh = K >> 5;
    load_buf(0, 0);
    for (int c = 0; c < nCh; c++) {
        if (c + 1 < nCh) { load_buf((c + 1) & 1, (c + 1) << 5); cp_wait<1>(); }
        else             { cp_wait<0>(); }
        __syncthreads();
        const uint32_t s0 = sb + (c & 1) * M1_BUF;
#pragma unroll
        for (int ks = 0; ks < 2; ks++) {
            const uint32_t kb = ks * 32 + t * 4;
            uint32_t ap[2][4];
#pragma unroll
            for (int mt = 0; mt < 2; mt++) {
                const uint32_t ra = s0 + (wy * 32 + mt * 16 + g) * MMA_RS + kb;
                ap[mt][0] = lds32(ra);
                ap[mt][1] = lds32(ra + 8 * MMA_RS);
                ap[mt][2] = lds32(ra + 16);
                ap[mt][3] = lds32(ra + 8 * MMA_RS + 16);
            }
#pragma unroll
            for (int nt = 0; nt < 8; nt++) {
                const uint32_t rb = s0 + MMA_ARR + (wx * 64 + nt * 8 + g) * MMA_RS + kb;
                uint32_t bb[2];
                bb[0] = lds32(rb); bb[1] = lds32(rb + 16);
                mma16816h(acc[0][nt], ap[0], bb);
                mma16816h(acc[1][nt], ap[1], bb);
            }
        }
        __syncthreads();
    }

#pragma unroll
    for (int mt = 0; mt < 2; mt++) {
        const int row = wy * 32 + mt * 16 + g;
#pragma unroll
        for (int nt = 0; nt < 8; nt++) {
            const int col = wx * 64 + nt * 8 + 2 * t;
            *(float2*)(Cb + (size_t)row * ldC + col) =
                make_float2(acc[mt][nt][0] * alpha, acc[mt][nt][1] * alpha);
            *(float2*)(Cb + (size_t)(row + 8) * ldC + col) =
                make_float2(acc[mt][nt][2] * alpha, acc[mt][nt][3] * alpha);
        }
    }
}

// ---------------- projection 3xBF16 GEMM: K=256, N=256, bias, opt residual ------
// OUT_MODE: 0 = fp32 (V), 1 = bf16 hi/lo (H), 2 = fp16 single (q, k).
template<bool HAS_ADD, int OUT_MODE>
__global__ void __launch_bounds__(256, 2) mma3p_kernel(
    const __nv_bfloat16* __restrict__ Ah, const __nv_bfloat16* __restrict__ Al,
    const __nv_bfloat16* __restrict__ Bh, const __nv_bfloat16* __restrict__ Bl,
    const float* __restrict__ bias, const float* __restrict__ X,
    float* __restrict__ Cf,
    __nv_bfloat16* __restrict__ Ch, __nv_bfloat16* __restrict__ Cl,
    __half* __restrict__ C16)
{
    extern __shared__ __align__(16) char smem[];
    const int tid  = threadIdx.x;
    const int lane = tid & 31, wid = tid >> 5;
    const int wy = wid >> 1, wx = wid & 1;
    const int g = lane >> 2, t = lane & 3;

    const int m0 = blockIdx.y * 128;
    const int n0 = blockIdx.x * 128;
    const size_t aBase = (size_t)m0 * F_DIM;
    const size_t bBase = (size_t)n0 * F_DIM;

    MMA3_MAINLOOP(F_DIM, F_DIM, F_DIM, aBase, bBase)

#pragma unroll
    for (int mt = 0; mt < 2; mt++) {
        const int r0 = m0 + wy * 32 + mt * 16 + g;
#pragma unroll
        for (int nt = 0; nt < 8; nt++) {
            const int gc = n0 + wx * 64 + nt * 8 + 2 * t;
            const float b0 = __ldg(bias + gc), b1 = __ldg(bias + gc + 1);
            float v00 = acc[mt][nt][0] + b0, v01 = acc[mt][nt][1] + b1;
            float v10 = acc[mt][nt][2] + b0, v11 = acc[mt][nt][3] + b1;
            if (HAS_ADD) {
                float2 x0 = *(const float2*)(X + (size_t)r0 * F_DIM + gc);
                float2 x1 = *(const float2*)(X + (size_t)(r0 + 8) * F_DIM + gc);
                v00 += x0.x; v01 += x0.y; v10 += x1.x; v11 += x1.y;
            }
            if (OUT_MODE == 1) {
                __nv_bfloat16 h00, l00, h01, l01, h10, l10, h11, l11;
                split1(v00, h00, l00); split1(v01, h01, l01);
                split1(v10, h10, l10); split1(v11, h11, l11);
                *(unsigned*)(Ch + (size_t)r0 * F_DIM + gc)       = pk2(h00, h01);
                *(unsigned*)(Cl + (size_t)r0 * F_DIM + gc)       = pk2(l00, l01);
                *(unsigned*)(Ch + (size_t)(r0 + 8) * F_DIM + gc) = pk2(h10, h11);
                *(unsigned*)(Cl + (size_t)(r0 + 8) * F_DIM + gc) = pk2(l10, l11);
            } else if (OUT_MODE == 2) {
                *(unsigned*)(C16 + (size_t)r0 * F_DIM + gc) =
                    pk2h(__float2half_rn(v00), __float2half_rn(v01));
                *(unsigned*)(C16 + (size_t)(r0 + 8) * F_DIM + gc) =
                    pk2h(__float2half_rn(v10), __float2half_rn(v11));
            } else {
                *(float2*)(Cf + (size_t)r0 * F_DIM + gc)       = make_float2(v00, v01);
                *(float2*)(Cf + (size_t)(r0 + 8) * F_DIM + gc) = make_float2(v10, v11);
            }
        }
    }
}

// ---------------- rowwise softmax -> P fp16 (single) ----------------
__global__ void softmax_kernel(const float* __restrict__ S, __half* __restrict__ ph) {
    __shared__ float red[8];
    const size_t row = blockIdx.x;
    const float4* r = (const float4*)(S + row * (size_t)N_SEQ);
    const int tid = threadIdx.x;        // 256 threads, 8 floats each
    float4 v0 = r[tid * 2], v1 = r[tid * 2 + 1];

    float m = fmaxf(fmaxf(fmaxf(v0.x, v0.y), fmaxf(v0.z, v0.w)),
                    fmaxf(fmaxf(v1.x, v1.y), fmaxf(v1.z, v1.w)));
#pragma unroll
    for (int o = 16; o; o >>= 1) m = fmaxf(m, __shfl_xor_sync(0xffffffffu, m, o));
    if ((tid & 31) == 0) red[tid >> 5] = m;
    __syncthreads();
    float mm = red[0];
#pragma unroll
    for (int i = 1; i < 8; i++) mm = fmaxf(mm, red[i]);
    __syncthreads();

    v0.x = __expf(v0.x - mm); v0.y = __expf(v0.y - mm);
    v0.z = __expf(v0.z - mm); v0.w = __expf(v0.w - mm);
    v1.x = __expf(v1.x - mm); v1.y = __expf(v1.y - mm);
    v1.z = __expf(v1.z - mm); v1.w = __expf(v1.w - mm);

    float s = ((v0.x + v0.y) + (v0.z + v0.w)) + ((v1.x + v1.y) + (v1.z + v1.w));
#pragma unroll
    for (int o = 16; o; o >>= 1) s += __shfl_xor_sync(0xffffffffu, s, o);
    if ((tid & 31) == 0) red[tid >> 5] = s;
    __syncthreads();
    float tot = ((red[0] + red[1]) + (red[2] + red[3])) +
                ((red[4] + red[5]) + (red[6] + red[7]));
    float inv = __frcp_rn(tot);

    float f[8] = {v0.x * inv, v0.y * inv, v0.z * inv, v0.w * inv,
                  v1.x * inv, v1.y * inv, v1.z * inv, v1.w * inv};
    __half h[8];
#pragma unroll
    for (int j = 0; j < 8; j++) h[j] = __float2half_rn(f[j]);
    const size_t base = row * (size_t)N_SEQ + tid * 8;
    uint4 H;
    H.x = pk2h(h[0], h[1]); H.y = pk2h(h[2], h[3]);
    H.z = pk2h(h[4], h[5]); H.w = pk2h(h[6], h[7]);
    *(uint4*)(ph + base) = H;
}

// ---------------- launch ----------------
extern "C" void kernel_launch(void* const* d_in, const int* in_sizes, int n_in,
                              void* d_out, int out_size) {
    const float* x  = (const float*)d_in[0];
    const float* p  = (const float*)d_in[1];
    const float* Wq = (const float*)d_in[2];
    const float* bq = (const float*)d_in[3];
    const float* Wk = (const float*)d_in[4];
    const float* bk = (const float*)d_in[5];
    const float* Wv = (const float*)d_in[6];
    const float* bv = (const float*)d_in[7];
    const float* W1 = (const float*)d_in[8];
    const float* b1 = (const float*)d_in[9];
    const float* W2 = (const float*)d_in[10];
    const float* b2 = (const float*)d_in[11];
    float* out = (float*)d_out;

    float *vbuf, *sbuf;
    __nv_bfloat16 *rh, *rl, *hh, *hl;
    __half *q16, *k16, *vt16, *p16;
    __nv_bfloat16 *w2h, *w2l, *wbh, *wbl, *wch, *wcl, *wdh, *wdl;
    cudaGetSymbolAddress((void**)&vbuf, g_v);
    cudaGetSymbolAddress((void**)&sbuf, g_s);
    cudaGetSymbolAddress((void**)&rh, g_rh);   cudaGetSymbolAddress((void**)&rl, g_rl);
    cudaGetSymbolAddress((void**)&hh, g_hh);   cudaGetSymbolAddress((void**)&hl, g_hl);
    cudaGetSymbolAddress((void**)&q16, g_q16); cudaGetSymbolAddress((void**)&k16, g_k16);
    cudaGetSymbolAddress((void**)&vt16, g_vt16);
    cudaGetSymbolAddress((void**)&p16, g_p16);
    cudaGetSymbolAddress((void**)&w2h, g_w2h); cudaGetSymbolAddress((void**)&w2l, g_w2l);
    cudaGetSymbolAddress((void**)&wbh, g_wbh); cudaGetSymbolAddress((void**)&wbl, g_wbl);
    cudaGetSymbolAddress((void**)&wch, g_wch); cudaGetSymbolAddress((void**)&wcl, g_wcl);
    cudaGetSymbolAddress((void**)&wdh, g_wdh); cudaGetSymbolAddress((void**)&wdl, g_wdl);

    cudaFuncSetAttribute(mma1_kernel, cudaFuncAttributeMaxDynamicSharedMemorySize, M1_SMEM);
    cudaFuncSetAttribute(mma3p_kernel<true, 1>,
                         cudaFuncAttributeMaxDynamicSharedMemorySize, MMA_SMEM);
    cudaFuncSetAttribute(mma3p_kernel<false, 2>,
                         cudaFuncAttributeMaxDynamicSharedMemorySize, MMA_SMEM);
    cudaFuncSetAttribute(mma3p_kernel<false, 0>,
                         cudaFuncAttributeMaxDynamicSharedMemorySize, MMA_SMEM);

    // 1) R = relu(p @ W1^T + b1) -> bf16 hi/lo
    pos_split_kernel<<<(BNR * 64) / 256, 256>>>(p, W1, b1, rh, rl);

    // 1b) weight splits in one launch (reference swaps: q-proj uses Wk, k-proj uses Wq)
    split4_kernel<<<dim3((F_DIM * F_DIM) / 1024, 4), 256>>>(
        W2, Wk, Wq, Wv, w2h, w2l, wbh, wbl, wch, wcl, wdh, wdl);

    // 2) H = R @ W2^T + b2 + x  -> bf16 hi/lo
    mma3p_kernel<true, 1><<<dim3(2, BNR / 128), 256, MMA_SMEM>>>(
        rh, rl, w2h, w2l, b2, x, nullptr, hh, hl, nullptr);

    // 3) projections from H (all HMMA); q,k emit fp16 single, v fp32
    mma3p_kernel<false, 2><<<dim3(2, BNR / 128), 256, MMA_SMEM>>>(
        hh, hl, wbh, wbl, bk, nullptr, nullptr, nullptr, nullptr, q16);  // q = H@Wk^T+bk
    mma3p_kernel<false, 2><<<dim3(2, BNR / 128), 256, MMA_SMEM>>>(
        hh, hl, wch, wcl, bq, nullptr, nullptr, nullptr, nullptr, k16);  // k = H@Wq^T+bq
    mma3p_kernel<false, 0><<<dim3(2, BNR / 128), 256, MMA_SMEM>>>(
        hh, hl, wdh, wdl, bv, nullptr, vbuf, nullptr, nullptr, nullptr); // v fp32

    // 4) V^T fp16 single
    vt_kernel<<<dim3(F_DIM / 32, BNR / 32), dim3(32, 8)>>>(vbuf, vt16);

    // 5) S = QK^T / 16  (1-pass fp16)
    mma1_kernel<<<dim3(16, 16, 16), 256, M1_SMEM>>>(
        q16, k16, sbuf,
        F_DIM, F_DIM, N_SEQ,
        (size_t)N_SEQ * F_DIM, (size_t)N_SEQ * F_DIM, (size_t)N_SEQ * N_SEQ, 0.0625f);

    // 6) softmax -> P fp16
    softmax_kernel<<<B_SZ * N_SEQ, 256>>>(sbuf, p16);

    // 7) out = P @ V  (1-pass fp16; B = V^T rows, ldB = BNR)
    mma1_kernel<<<dim3(F_DIM / 128, 16, 16), 256, M1_SMEM>>>(
        p16, vt16, out,
        N_SEQ, BNR, F_DIM,
        (size_t)N_SEQ * N_SEQ, (size_t)N_SEQ, (size_t)N_SEQ * F_DIM, 1.0f);
}